// round 7
// baseline (speedup 1.0000x reference)
#include <cuda_runtime.h>
#include <cstdint>

#define NN_ 20000
#define KNB 32
#define DD  128
#define SA  132

__device__ float g_tsf[(size_t)NN_ * DD];
__device__ float g_ts[NN_];

__device__ __forceinline__ float sigf(float x){ return 1.0f/(1.0f+__expf(-x)); }
__device__ __forceinline__ uint32_t f2tf(float f){ uint32_t o; asm("cvt.rna.tf32.f32 %0, %1;":"=r"(o):"f"(f)); return o; }
__device__ __forceinline__ void cp16(uint32_t s, const void* g){
    asm volatile("cp.async.cg.shared.global [%0], [%1], 16;"::"r"(s),"l"(g));
}
__device__ __forceinline__ void mma_tf32(float c[4], const uint32_t a[4], uint32_t b0, uint32_t b1){
    asm volatile("mma.sync.aligned.m16n8k8.row.col.f32.tf32.tf32.f32 "
        "{%0,%1,%2,%3},{%4,%5,%6,%7},{%8,%9},{%0,%1,%2,%3};"
        : "+f"(c[0]),"+f"(c[1]),"+f"(c[2]),"+f"(c[3])
        : "r"(a[0]),"r"(a[1]),"r"(a[2]),"r"(a[3]),"r"(b0),"r"(b1));
}

// ---------------- Kernel 1: tsf = sf @ SW ; ts = sv . gsw ----------------
__global__ void __launch_bounds__(128)
precompute_kernel(const float* __restrict__ sf, const float* __restrict__ sv,
                  const float* __restrict__ SW, const float* __restrict__ gsw){
    __shared__ float sf_s[32][128];
    __shared__ float sv_s[32][128];
    const int tid = threadIdx.x;
    const int n0 = blockIdx.x * 32;
    {
        const float4* a = (const float4*)(sf + (size_t)n0*DD);
        const float4* b = (const float4*)(sv + (size_t)n0*DD);
        float4* as = (float4*)&sf_s[0][0];
        float4* bs = (float4*)&sv_s[0][0];
#pragma unroll
        for (int i=0;i<8;i++){ int c = tid + i*128; as[c]=a[c]; bs[c]=b[c]; }
    }
    __syncthreads();
    const int lane = tid & 31, wp = tid >> 5;
    const float4* SW4 = (const float4*)SW;
    float4 acc[8];
#pragma unroll
    for (int r=0;r<8;r++) acc[r] = make_float4(0.f,0.f,0.f,0.f);
#pragma unroll 4
    for (int e=0;e<128;e++){
        float4 w4 = SW4[e*32 + lane];
#pragma unroll
        for (int r=0;r<8;r++){
            float s = sf_s[wp*8+r][e];
            acc[r].x += s*w4.x; acc[r].y += s*w4.y; acc[r].z += s*w4.z; acc[r].w += s*w4.w;
        }
    }
    float4* outt = (float4*)g_tsf;
#pragma unroll
    for (int r=0;r<8;r++) outt[(size_t)(n0+wp*8+r)*32 + lane] = acc[r];
    // ts: 4 threads per row
    {
        const int r = tid >> 2, q4 = tid & 3;
        float p = 0.f;
#pragma unroll
        for (int j=0;j<8;j++){
            float4 v = *(const float4*)(&sv_s[r][q4*32 + j*4]);
            float4 g = *(const float4*)(gsw + q4*32 + j*4);
            p += v.x*g.x + v.y*g.y + v.z*g.z + v.w*g.w;
        }
        p += __shfl_xor_sync(0xffffffffu, p, 1);
        p += __shfl_xor_sync(0xffffffffu, p, 2);
        if (q4 == 0) g_ts[n0 + r] = p;
    }
}

// ---------------- Main persistent kernel ----------------
#define LINK0  0
#define NEIGH0 4224
#define LINK1  8448
#define NEIGH1 12672
#define TSF0   16896
#define TSF1   17024
#define PRB0   17152
#define PRB1   17184
#define WSK    17216
#define SMEM_FLOATS 17248
#define SMEM_BYTES  (SMEM_FLOATS*4)

__global__ void __launch_bounds__(256,1)
main_kernel(const float* __restrict__ neigh, const float* __restrict__ link,
            const float* __restrict__ probs, const float* __restrict__ gwn,
            const float* __restrict__ gwl, const float* __restrict__ Wlink,
            float* __restrict__ out){
    extern __shared__ float sb[];
    const int tid = threadIdx.x, lane = tid & 31, wid = tid >> 5;
    const uint32_t su = (uint32_t)__cvta_generic_to_shared(sb);

    // stage link_weights once (unpadded 128x128) and grab B frags into regs
    {
        float4* dst = (float4*)sb;
        const float4* src = (const float4*)Wlink;
#pragma unroll
        for (int i=0;i<16;i++) dst[tid + i*256] = src[tid + i*256];
    }
    __syncthreads();
    const int cb = wid * 16;                 // this warp's 16 output cols
    uint32_t bB[64];                         // [kk*4 + nt*2 + reg]
#pragma unroll
    for (int kk=0;kk<16;kk++){
#pragma unroll
        for (int nt=0;nt<2;nt++){
            int col = cb + nt*8 + (lane>>2);
            int r0  = kk*8 + (lane&3);
            bB[kk*4+nt*2+0] = f2tf(sb[ r0     *128 + col]);
            bB[kk*4+nt*2+1] = f2tf(sb[(r0+4)*128 + col]);
        }
    }
    __syncthreads();

    // gate weights per thread (16 elems each, qg = tid&7)
    const int qg = tid & 7, kg = tid >> 3;
    float4 gl4[4], gn4[4];
#pragma unroll
    for (int j=0;j<4;j++){
        gl4[j] = *(const float4*)(gwl + qg*16 + j*4);
        gn4[j] = *(const float4*)(gwn + qg*16 + j*4);
    }

    const int stride = gridDim.x;
    int n = blockIdx.x;
    int buf = 0;

    auto prefetch = [&](int node, int b){
        size_t base = (size_t)node * (KNB*DD);
        uint32_t sL = su + (uint32_t)((b?LINK1:LINK0)*4);
        uint32_t sN = su + (uint32_t)((b?NEIGH1:NEIGH0)*4);
#pragma unroll
        for (int i=0;i<4;i++){
            int c = tid + i*256;            // 1024 16B chunks per tile
            int row = c >> 5, col = c & 31;
            uint32_t off = (uint32_t)(row*SA + col*4)*4;
            cp16(sL + off, link  + base + row*128 + col*4);
            cp16(sN + off, neigh + base + row*128 + col*4);
        }
        if (tid < 32)
            cp16(su + (uint32_t)(((b?TSF1:TSF0) + tid*4)*4), g_tsf + (size_t)node*DD + tid*4);
        else if (tid < 40){
            int c = tid - 32;
            cp16(su + (uint32_t)(((b?PRB1:PRB0) + c*4)*4), probs + (size_t)node*KNB + c*4);
        }
    };

    prefetch(n, 0);
    asm volatile("cp.async.commit_group;");

    for (; n < NN_; n += stride, buf ^= 1){
        int nn = n + stride;
        if (nn < NN_) prefetch(nn, buf^1);
        asm volatile("cp.async.commit_group;");
        asm volatile("cp.async.wait_group 1;");
        __syncthreads();

        float* lk = sb + (buf?LINK1:LINK0);
        float* ng = sb + (buf?NEIGH1:NEIGH0);
        float* tf = sb + (buf?TSF1:TSF0);
        float* pb = sb + (buf?PRB1:PRB0);

        // gate weights per (node,k): 8 threads per k
        {
            float t = 0.f;
#pragma unroll
            for (int j=0;j<4;j++){
                float4 l4 = *(const float4*)(lk + kg*SA + qg*16 + j*4);
                float4 n4 = *(const float4*)(ng + kg*SA + qg*16 + j*4);
                t += l4.x*gl4[j].x + l4.y*gl4[j].y + l4.z*gl4[j].z + l4.w*gl4[j].w;
                t += n4.x*gn4[j].x + n4.y*gn4[j].y + n4.z*gn4[j].z + n4.w*gn4[j].w;
            }
            t += __shfl_xor_sync(0xffffffffu, t, 1);
            t += __shfl_xor_sync(0xffffffffu, t, 2);
            t += __shfl_xor_sync(0xffffffffu, t, 4);
            if (qg == 0){
                float ts = g_ts[n];
                sb[WSK + kg] = sigf(ts + t) / (pb[kg] * (float)KNB);
            }
        }

        // TF32 MMA: acc[mt][nt][4], A from padded smem (conflict-free)
        float acc[2][2][4];
#pragma unroll
        for (int mt=0;mt<2;mt++)
#pragma unroll
            for (int nt=0;nt<2;nt++)
#pragma unroll
                for (int r=0;r<4;r++) acc[mt][nt][r] = 0.f;

#pragma unroll
        for (int kk=0;kk<16;kk++){
#pragma unroll
            for (int mt=0;mt<2;mt++){
                int ar = mt*16 + (lane>>2);
                int ac = kk*8 + (lane&3);
                uint32_t aF[4];
                aF[0] = f2tf(lk[ ar   *SA + ac   ]);
                aF[1] = f2tf(lk[(ar+8)*SA + ac   ]);
                aF[2] = f2tf(lk[ ar   *SA + ac+4 ]);
                aF[3] = f2tf(lk[(ar+8)*SA + ac+4 ]);
                mma_tf32(acc[mt][0], aF, bB[kk*4+0], bB[kk*4+1]);
                mma_tf32(acc[mt][1], aF, bB[kk*4+2], bB[kk*4+3]);
            }
        }
        __syncthreads();   // WSK visible to all

        // epilogue: sum_k neigh*sigmoid(gemm)*w[k], reduce over k, relu(tsf*s)
        const int q = lane & 3;
        float s[2][2] = {{0.f,0.f},{0.f,0.f}};
#pragma unroll
        for (int mt=0;mt<2;mt++){
            int r0 = mt*16 + (lane>>2), r1 = r0 + 8;
            float w0 = sb[WSK + r0], w1 = sb[WSK + r1];
#pragma unroll
            for (int nt=0;nt<2;nt++){
                int c0 = cb + nt*8 + 2*q;
                float2 n0 = *(const float2*)(ng + r0*SA + c0);
                float2 n1 = *(const float2*)(ng + r1*SA + c0);
                s[nt][0] += n0.x * sigf(acc[mt][nt][0]) * w0
                          + n1.x * sigf(acc[mt][nt][2]) * w1;
                s[nt][1] += n0.y * sigf(acc[mt][nt][1]) * w0
                          + n1.y * sigf(acc[mt][nt][3]) * w1;
            }
        }
#pragma unroll
        for (int nt=0;nt<2;nt++)
#pragma unroll
            for (int h=0;h<2;h++){
                s[nt][h] += __shfl_xor_sync(0xffffffffu, s[nt][h], 4);
                s[nt][h] += __shfl_xor_sync(0xffffffffu, s[nt][h], 8);
                s[nt][h] += __shfl_xor_sync(0xffffffffu, s[nt][h], 16);
            }
        if (lane < 4){
#pragma unroll
            for (int nt=0;nt<2;nt++){
                int c0 = cb + nt*8 + 2*lane;
                float v0 = tf[c0]   * s[nt][0];
                float v1 = tf[c0+1] * s[nt][1];
                float2 o; o.x = fmaxf(v0, 0.f); o.y = fmaxf(v1, 0.f);
                *(float2*)(out + (size_t)n*DD + c0) = o;
            }
        }
        __syncthreads();   // protect buffers before next prefetch overwrite
    }
}

extern "C" void kernel_launch(void* const* d_in, const int* in_sizes, int n_in,
                              void* d_out, int out_size){
    const float* self_feats  = (const float*)d_in[0];
    const float* self_vecs   = (const float*)d_in[1];
    const float* neigh_vecs  = (const float*)d_in[2];
    const float* link_vecs   = (const float*)d_in[3];
    const float* select_pr   = (const float*)d_in[4];
    const float* gate_self_w = (const float*)d_in[5];
    const float* gate_neigh_w= (const float*)d_in[6];
    const float* gate_link_w = (const float*)d_in[7];
    const float* self_w      = (const float*)d_in[8];
    const float* link_w      = (const float*)d_in[9];
    float* out = (float*)d_out;
    (void)in_sizes; (void)n_in; (void)out_size;

    cudaFuncSetAttribute(main_kernel, cudaFuncAttributeMaxDynamicSharedMemorySize, SMEM_BYTES);

    int dev = 0, sms = 148;
    cudaGetDevice(&dev);
    cudaDeviceGetAttribute(&sms, cudaDevAttrMultiProcessorCount, dev);

    precompute_kernel<<<NN_/32, 128>>>(self_feats, self_vecs, self_w, gate_self_w);
    main_kernel<<<sms, 256, SMEM_BYTES>>>(neigh_vecs, link_vecs, select_pr,
                                          gate_neigh_w, gate_link_w, link_w, out);
}

// round 8
// speedup vs baseline: 1.1177x; 1.1177x over previous
#include <cuda_runtime.h>
#include <cstdint>

#define NN_  20000
#define KNB  32
#define DD   128
#define SA   132
#define NPAIR (NN_/2)

__device__ float g_tsf[(size_t)NN_ * DD];
__device__ float g_ts[NN_];

__device__ __forceinline__ float sigf(float x){ return 1.0f/(1.0f+__expf(-x)); }
__device__ __forceinline__ uint32_t f2tf(float f){ uint32_t o; asm("cvt.rna.tf32.f32 %0, %1;":"=r"(o):"f"(f)); return o; }
__device__ __forceinline__ void cp16(uint32_t s, const void* g){
    asm volatile("cp.async.cg.shared.global [%0], [%1], 16;"::"r"(s),"l"(g));
}
__device__ __forceinline__ void mma_tf32(float c[4], const uint32_t a[4], uint32_t b0, uint32_t b1){
    asm volatile("mma.sync.aligned.m16n8k8.row.col.f32.tf32.tf32.f32 "
        "{%0,%1,%2,%3},{%4,%5,%6,%7},{%8,%9},{%0,%1,%2,%3};"
        : "+f"(c[0]),"+f"(c[1]),"+f"(c[2]),"+f"(c[3])
        : "r"(a[0]),"r"(a[1]),"r"(a[2]),"r"(a[3]),"r"(b0),"r"(b1));
}

// ============ Kernel 1: tsf = sf @ SW (TF32 MMA) ; ts = sv . gsw ============
// smem: SW staging [0,16384) ; sf padded tile [16384, 16384+4224) ; pack [20608, 24704)
#define P_TILE 16384
#define P_PACK (16384+4224)
#define P_FLOATS (P_PACK+4096)
#define P_BYTES (P_FLOATS*4)

__global__ void __launch_bounds__(256,1)
precompute_kernel(const float* __restrict__ sf, const float* __restrict__ sv,
                  const float* __restrict__ SW, const float* __restrict__ gsw){
    extern __shared__ float ps[];
    const int tid = threadIdx.x, lane = tid & 31, wid = tid >> 5;
    const int n0 = blockIdx.x * 32;

    { // stage SW
        float4* dst = (float4*)ps;
        const float4* src = (const float4*)SW;
#pragma unroll
        for (int i=0;i<16;i++) dst[tid + i*256] = src[tid + i*256];
    }
    __syncthreads();
    const int cb = wid * 16;
    uint32_t bB[64];
#pragma unroll
    for (int kk=0;kk<16;kk++)
#pragma unroll
        for (int nt=0;nt<2;nt++){
            int col = cb + nt*8 + (lane>>2);
            int r0  = kk*8 + (lane&3);
            bB[kk*4+nt*2+0] = f2tf(ps[ r0    *128 + col]);
            bB[kk*4+nt*2+1] = f2tf(ps[(r0+4)*128 + col]);
        }
    __syncthreads();

    { // load sf tile (32x128) into padded region
        const float4* src = (const float4*)(sf + (size_t)n0*DD);
#pragma unroll
        for (int i=0;i<4;i++){
            int c = tid + i*256, row = c>>5, col = c&31;
            *(float4*)(ps + P_TILE + row*SA + col*4) = src[c];
        }
    }
    __syncthreads();
    { // pack tf32 fragments
#pragma unroll
        for (int q=0;q<4;q++){
            int S = tid + q*256;
            int kk = S>>6, mt = (S>>5)&1, l = S&31;
            int r = mt*16 + (l>>2), c = kk*8 + (l&3);
            const float* t = ps + P_TILE;
            float4 v;
            v.x = __uint_as_float(f2tf(t[ r   *SA + c  ]));
            v.y = __uint_as_float(f2tf(t[(r+8)*SA + c  ]));
            v.z = __uint_as_float(f2tf(t[ r   *SA + c+4]));
            v.w = __uint_as_float(f2tf(t[(r+8)*SA + c+4]));
            *(float4*)(ps + P_PACK + S*4) = v;
        }
    }
    __syncthreads();

    float acc[2][2][4];
#pragma unroll
    for (int mt=0;mt<2;mt++)
#pragma unroll
        for (int nt=0;nt<2;nt++)
#pragma unroll
            for (int j=0;j<4;j++) acc[mt][nt][j]=0.f;
#pragma unroll
    for (int kk=0;kk<16;kk++)
#pragma unroll
        for (int mt=0;mt<2;mt++){
            float4 f = *(const float4*)(ps + P_PACK + ((kk*2+mt)*32+lane)*4);
            uint32_t a[4] = {__float_as_uint(f.x),__float_as_uint(f.y),
                             __float_as_uint(f.z),__float_as_uint(f.w)};
            mma_tf32(acc[mt][0], a, bB[kk*4+0], bB[kk*4+1]);
            mma_tf32(acc[mt][1], a, bB[kk*4+2], bB[kk*4+3]);
        }
    // write tsf
#pragma unroll
    for (int mt=0;mt<2;mt++)
#pragma unroll
        for (int nt=0;nt<2;nt++){
            int row = mt*16 + (lane>>2), col = cb + nt*8 + 2*(lane&3);
            float2 v0 = {acc[mt][nt][0], acc[mt][nt][1]};
            float2 v1 = {acc[mt][nt][2], acc[mt][nt][3]};
            *(float2*)(g_tsf + (size_t)(n0+row  )*DD + col) = v0;
            *(float2*)(g_tsf + (size_t)(n0+row+8)*DD + col) = v1;
        }
    // ts = sv . gsw : 8 threads per row
    {
        const int r = tid>>3, q = tid&7;
        const float* svr = sv + (size_t)(n0+r)*DD + q*16;
        float t = 0.f;
#pragma unroll
        for (int j=0;j<4;j++){
            float4 v = *(const float4*)(svr + j*4);
            float4 g = *(const float4*)(gsw + q*16 + j*4);
            t += v.x*g.x + v.y*g.y + v.z*g.z + v.w*g.w;
        }
        t += __shfl_xor_sync(0xffffffffu, t, 1);
        t += __shfl_xor_sync(0xffffffffu, t, 2);
        t += __shfl_xor_sync(0xffffffffu, t, 4);
        if (q == 0) g_ts[n0 + r] = t;
    }
}

// ============ Main persistent kernel: 2 nodes/iteration, 4 smem stages ============
#define STGF 8640
#define LKo(s) ((s)*STGF)
#define NGo(s) ((s)*STGF+4224)
#define TFo(s) ((s)*STGF+8448)
#define PBo(s) ((s)*STGF+8576)
#define WSo(s) ((s)*STGF+8608)
#define PACKA 34560
#define PACKB 38656
#define SMEMF 42752
#define SMEM_BYTES (SMEMF*4)

__global__ void __launch_bounds__(256,1)
main_kernel(const float* __restrict__ neigh, const float* __restrict__ link,
            const float* __restrict__ probs, const float* __restrict__ gwn,
            const float* __restrict__ gwl, const float* __restrict__ Wlink,
            float* __restrict__ out){
    extern __shared__ float sb[];
    const int tid = threadIdx.x, lane = tid & 31, wid = tid >> 5;
    const uint32_t su = (uint32_t)__cvta_generic_to_shared(sb);

    { // stage link_weights once; build B fragments in registers
        float4* dst = (float4*)sb;
        const float4* src = (const float4*)Wlink;
#pragma unroll
        for (int i=0;i<16;i++) dst[tid + i*256] = src[tid + i*256];
    }
    __syncthreads();
    const int cb = wid * 16;
    uint32_t bB[64];
#pragma unroll
    for (int kk=0;kk<16;kk++)
#pragma unroll
        for (int nt=0;nt<2;nt++){
            int col = cb + nt*8 + (lane>>2);
            int r0  = kk*8 + (lane&3);
            bB[kk*4+nt*2+0] = f2tf(sb[ r0    *128 + col]);
            bB[kk*4+nt*2+1] = f2tf(sb[(r0+4)*128 + col]);
        }
    __syncthreads();

    const int qg = tid & 7, kg = tid >> 3;
    float4 gl4[4], gn4[4];
#pragma unroll
    for (int j=0;j<4;j++){
        gl4[j] = *(const float4*)(gwl + qg*16 + j*4);
        gn4[j] = *(const float4*)(gwn + qg*16 + j*4);
    }

    const int s2 = gridDim.x;
    int p = blockIdx.x;
    int buf = 0;

    auto prefetch = [&](int pair, int b){
#pragma unroll
        for (int x=0;x<2;x++){
            int st = b*2 + x;
            size_t base = (size_t)(pair*2 + x) * (KNB*DD);
            uint32_t sL = su + (uint32_t)(LKo(st)*4);
            uint32_t sN = su + (uint32_t)(NGo(st)*4);
#pragma unroll
            for (int i=0;i<4;i++){
                int c = tid + i*256, row = c>>5, col = c&31;
                uint32_t off = (uint32_t)(row*SA + col*4)*4;
                cp16(sL + off, link  + base + row*128 + col*4);
                cp16(sN + off, neigh + base + row*128 + col*4);
            }
        }
        int nA = pair*2;
        if (tid < 32)
            cp16(su + (uint32_t)((TFo(b*2)   + tid*4)*4), g_tsf + (size_t)nA*DD + tid*4);
        else if (tid < 40)
            cp16(su + (uint32_t)((PBo(b*2)   + (tid-32)*4)*4), probs + (size_t)nA*KNB + (tid-32)*4);
        else if (tid >= 64 && tid < 96)
            cp16(su + (uint32_t)((TFo(b*2+1) + (tid-64)*4)*4), g_tsf + (size_t)(nA+1)*DD + (tid-64)*4);
        else if (tid >= 96 && tid < 104)
            cp16(su + (uint32_t)((PBo(b*2+1) + (tid-96)*4)*4), probs + (size_t)(nA+1)*KNB + (tid-96)*4);
    };

    prefetch(p, 0);
    asm volatile("cp.async.commit_group;");

    for (; p < NPAIR; p += s2, buf ^= 1){
        int pn = p + s2;
        if (pn < NPAIR) prefetch(pn, buf^1);
        asm volatile("cp.async.commit_group;");
        asm volatile("cp.async.wait_group 1;");
        __syncthreads();

        const int stA = buf*2, stB = buf*2+1;
        const int nA = p*2, nB = nA+1;
        float* lkS[2] = { sb + LKo(stA), sb + LKo(stB) };
        float* ngS[2] = { sb + NGo(stA), sb + NGo(stB) };

        // ---- gate dots for both nodes (8 threads per k) ----
        {
            float tA = 0.f, tB = 0.f;
#pragma unroll
            for (int j=0;j<4;j++){
                float4 lA = *(const float4*)(lkS[0] + kg*SA + qg*16 + j*4);
                float4 nAv= *(const float4*)(ngS[0] + kg*SA + qg*16 + j*4);
                float4 lB = *(const float4*)(lkS[1] + kg*SA + qg*16 + j*4);
                float4 nBv= *(const float4*)(ngS[1] + kg*SA + qg*16 + j*4);
                tA += lA.x*gl4[j].x + lA.y*gl4[j].y + lA.z*gl4[j].z + lA.w*gl4[j].w
                    + nAv.x*gn4[j].x + nAv.y*gn4[j].y + nAv.z*gn4[j].z + nAv.w*gn4[j].w;
                tB += lB.x*gl4[j].x + lB.y*gl4[j].y + lB.z*gl4[j].z + lB.w*gl4[j].w
                    + nBv.x*gn4[j].x + nBv.y*gn4[j].y + nBv.z*gn4[j].z + nBv.w*gn4[j].w;
            }
            tA += __shfl_xor_sync(0xffffffffu, tA, 1);
            tB += __shfl_xor_sync(0xffffffffu, tB, 1);
            tA += __shfl_xor_sync(0xffffffffu, tA, 2);
            tB += __shfl_xor_sync(0xffffffffu, tB, 2);
            tA += __shfl_xor_sync(0xffffffffu, tA, 4);
            tB += __shfl_xor_sync(0xffffffffu, tB, 4);
            if (qg == 0){
                sb[WSo(stA) + kg] = sigf(g_ts[nA] + tA) / (sb[PBo(stA)+kg] * (float)KNB);
                sb[WSo(stB) + kg] = sigf(g_ts[nB] + tB) / (sb[PBo(stB)+kg] * (float)KNB);
            }
        }

        // ---- pack tf32 A fragments for both nodes (each element cvt'd once) ----
#pragma unroll
        for (int q=0;q<4;q++){
            int S = tid + q*256;
            int kk = S>>6, mt = (S>>5)&1, l = S&31;
            int r = mt*16 + (l>>2), c = kk*8 + (l&3);
            float4 vA, vB;
            vA.x = __uint_as_float(f2tf(lkS[0][ r   *SA + c  ]));
            vA.y = __uint_as_float(f2tf(lkS[0][(r+8)*SA + c  ]));
            vA.z = __uint_as_float(f2tf(lkS[0][ r   *SA + c+4]));
            vA.w = __uint_as_float(f2tf(lkS[0][(r+8)*SA + c+4]));
            vB.x = __uint_as_float(f2tf(lkS[1][ r   *SA + c  ]));
            vB.y = __uint_as_float(f2tf(lkS[1][(r+8)*SA + c  ]));
            vB.z = __uint_as_float(f2tf(lkS[1][ r   *SA + c+4]));
            vB.w = __uint_as_float(f2tf(lkS[1][(r+8)*SA + c+4]));
            *(float4*)(sb + PACKA + S*4) = vA;
            *(float4*)(sb + PACKB + S*4) = vB;
        }
        __syncthreads();

        // ---- MMA: both nodes interleaved, shared B frags ----
        float acc[2][2][2][4];   // [node][mt][nt][j]
#pragma unroll
        for (int x=0;x<2;x++)
#pragma unroll
            for (int mt=0;mt<2;mt++)
#pragma unroll
                for (int nt=0;nt<2;nt++)
#pragma unroll
                    for (int j=0;j<4;j++) acc[x][mt][nt][j]=0.f;
#pragma unroll
        for (int kk=0;kk<16;kk++)
#pragma unroll
            for (int mt=0;mt<2;mt++){
                float4 fA = *(const float4*)(sb + PACKA + ((kk*2+mt)*32+lane)*4);
                float4 fB = *(const float4*)(sb + PACKB + ((kk*2+mt)*32+lane)*4);
                uint32_t aA[4] = {__float_as_uint(fA.x),__float_as_uint(fA.y),
                                  __float_as_uint(fA.z),__float_as_uint(fA.w)};
                uint32_t aB[4] = {__float_as_uint(fB.x),__float_as_uint(fB.y),
                                  __float_as_uint(fB.z),__float_as_uint(fB.w)};
                mma_tf32(acc[0][mt][0], aA, bB[kk*4+0], bB[kk*4+1]);
                mma_tf32(acc[1][mt][0], aB, bB[kk*4+0], bB[kk*4+1]);
                mma_tf32(acc[0][mt][1], aA, bB[kk*4+2], bB[kk*4+3]);
                mma_tf32(acc[1][mt][1], aB, bB[kk*4+2], bB[kk*4+3]);
            }

        // ---- epilogue, both nodes ----
        const int q = lane & 3;
#pragma unroll
        for (int x=0;x<2;x++){
            const int st = buf*2 + x;
            const float* ng_ = ngS[x];
            const float* ws_ = sb + WSo(st);
            const float* tf_ = sb + TFo(st);
            float s[2][2] = {{0.f,0.f},{0.f,0.f}};
#pragma unroll
            for (int mt=0;mt<2;mt++){
                int r0 = mt*16 + (lane>>2), r1 = r0 + 8;
                float w0 = ws_[r0], w1 = ws_[r1];
#pragma unroll
                for (int nt=0;nt<2;nt++){
                    int c0 = cb + nt*8 + 2*q;
                    float2 n0 = *(const float2*)(ng_ + r0*SA + c0);
                    float2 n1 = *(const float2*)(ng_ + r1*SA + c0);
                    s[nt][0] += n0.x * sigf(acc[x][mt][nt][0]) * w0
                              + n1.x * sigf(acc[x][mt][nt][2]) * w1;
                    s[nt][1] += n0.y * sigf(acc[x][mt][nt][1]) * w0
                              + n1.y * sigf(acc[x][mt][nt][3]) * w1;
                }
            }
#pragma unroll
            for (int nt=0;nt<2;nt++)
#pragma unroll
                for (int h=0;h<2;h++){
                    s[nt][h] += __shfl_xor_sync(0xffffffffu, s[nt][h], 4);
                    s[nt][h] += __shfl_xor_sync(0xffffffffu, s[nt][h], 8);
                    s[nt][h] += __shfl_xor_sync(0xffffffffu, s[nt][h], 16);
                }
            if (lane < 4){
#pragma unroll
                for (int nt=0;nt<2;nt++){
                    int c0 = cb + nt*8 + 2*lane;
                    float2 o;
                    o.x = fmaxf(tf_[c0]   * s[nt][0], 0.f);
                    o.y = fmaxf(tf_[c0+1] * s[nt][1], 0.f);
                    *(float2*)(out + (size_t)(nA+x)*DD + c0) = o;
                }
            }
        }
        __syncthreads();   // protect stage + pack buffers before reuse
    }
}

extern "C" void kernel_launch(void* const* d_in, const int* in_sizes, int n_in,
                              void* d_out, int out_size){
    const float* self_feats  = (const float*)d_in[0];
    const float* self_vecs   = (const float*)d_in[1];
    const float* neigh_vecs  = (const float*)d_in[2];
    const float* link_vecs   = (const float*)d_in[3];
    const float* select_pr   = (const float*)d_in[4];
    const float* gate_self_w = (const float*)d_in[5];
    const float* gate_neigh_w= (const float*)d_in[6];
    const float* gate_link_w = (const float*)d_in[7];
    const float* self_w      = (const float*)d_in[8];
    const float* link_w      = (const float*)d_in[9];
    float* out = (float*)d_out;
    (void)in_sizes; (void)n_in; (void)out_size;

    cudaFuncSetAttribute(precompute_kernel, cudaFuncAttributeMaxDynamicSharedMemorySize, P_BYTES);
    cudaFuncSetAttribute(main_kernel, cudaFuncAttributeMaxDynamicSharedMemorySize, SMEM_BYTES);

    int dev = 0, sms = 148;
    cudaGetDevice(&dev);
    cudaDeviceGetAttribute(&sms, cudaDevAttrMultiProcessorCount, dev);

    precompute_kernel<<<NN_/32, 256, P_BYTES>>>(self_feats, self_vecs, self_w, gate_self_w);
    main_kernel<<<sms, 256, SMEM_BYTES>>>(neigh_vecs, link_vecs, select_pr,
                                          gate_neigh_w, gate_link_w, link_w, out);
}

// round 10
// speedup vs baseline: 1.6933x; 1.5150x over previous
#include <cuda_runtime.h>
#include <cstdint>

#define NN_  20000
#define KNB  32
#define DD   128
#define SA   132

__device__ float g_tsf[(size_t)NN_ * DD];
__device__ float g_ts[NN_];

__device__ __forceinline__ float sigf(float x){ return 1.0f/(1.0f+__expf(-x)); }
__device__ __forceinline__ float sigt(float x){   // sigmoid via 1 MUFU (tanh.approx)
    float t; asm("tanh.approx.f32 %0, %1;" : "=f"(t) : "f"(0.5f*x));
    return fmaf(0.5f, t, 0.5f);
}
__device__ __forceinline__ uint32_t f2tf(float f){ uint32_t o; asm("cvt.rna.tf32.f32 %0, %1;":"=r"(o):"f"(f)); return o; }
__device__ __forceinline__ void cp16(uint32_t s, const void* g){
    asm volatile("cp.async.cg.shared.global [%0], [%1], 16;"::"r"(s),"l"(g));
}
__device__ __forceinline__ void mma_tf32(float c[4], const uint32_t a[4], uint32_t b0, uint32_t b1){
    asm volatile("mma.sync.aligned.m16n8k8.row.col.f32.tf32.tf32.f32 "
        "{%0,%1,%2,%3},{%4,%5,%6,%7},{%8,%9},{%0,%1,%2,%3};"
        : "+f"(c[0]),"+f"(c[1]),"+f"(c[2]),"+f"(c[3])
        : "r"(a[0]),"r"(a[1]),"r"(a[2]),"r"(a[3]),"r"(b0),"r"(b1));
}

// ============ Kernel 1: tsf = sf @ SW (TF32 MMA) ; ts = sv . gsw ============
#define P_TILE 16384
#define P_PACK (16384+4224)
#define P_FLOATS (P_PACK+4096)
#define P_BYTES (P_FLOATS*4)

__global__ void __launch_bounds__(256,1)
precompute_kernel(const float* __restrict__ sf, const float* __restrict__ sv,
                  const float* __restrict__ SW, const float* __restrict__ gsw){
    extern __shared__ float ps[];
    const int tid = threadIdx.x, lane = tid & 31, wid = tid >> 5;
    const int n0 = blockIdx.x * 32;

    {
        float4* dst = (float4*)ps;
        const float4* src = (const float4*)SW;
#pragma unroll
        for (int i=0;i<16;i++) dst[tid + i*256] = src[tid + i*256];
    }
    __syncthreads();
    const int cb = wid * 16;
    uint32_t bB[64];
#pragma unroll
    for (int kk=0;kk<16;kk++)
#pragma unroll
        for (int nt=0;nt<2;nt++){
            int col = cb + nt*8 + (lane>>2);
            int r0  = kk*8 + (lane&3);
            bB[kk*4+nt*2+0] = f2tf(ps[ r0    *128 + col]);
            bB[kk*4+nt*2+1] = f2tf(ps[(r0+4)*128 + col]);
        }
    __syncthreads();
    {
        const float4* src = (const float4*)(sf + (size_t)n0*DD);
#pragma unroll
        for (int i=0;i<4;i++){
            int c = tid + i*256, row = c>>5, col = c&31;
            *(float4*)(ps + P_TILE + row*SA + col*4) = src[c];
        }
    }
    __syncthreads();
    {
#pragma unroll
        for (int q=0;q<4;q++){
            int S = tid + q*256;
            int kk = S>>6, mt = (S>>5)&1, l = S&31;
            int r = mt*16 + (l>>2), c = kk*8 + (l&3);
            const float* t = ps + P_TILE;
            float4 v;
            v.x = __uint_as_float(f2tf(t[ r   *SA + c  ]));
            v.y = __uint_as_float(f2tf(t[(r+8)*SA + c  ]));
            v.z = __uint_as_float(f2tf(t[ r   *SA + c+4]));
            v.w = __uint_as_float(f2tf(t[(r+8)*SA + c+4]));
            *(float4*)(ps + P_PACK + S*4) = v;
        }
    }
    __syncthreads();

    float acc[2][2][4];
#pragma unroll
    for (int mt=0;mt<2;mt++)
#pragma unroll
        for (int nt=0;nt<2;nt++)
#pragma unroll
            for (int j=0;j<4;j++) acc[mt][nt][j]=0.f;
#pragma unroll
    for (int kk=0;kk<16;kk++)
#pragma unroll
        for (int mt=0;mt<2;mt++){
            float4 f = *(const float4*)(ps + P_PACK + ((kk*2+mt)*32+lane)*4);
            uint32_t a[4] = {__float_as_uint(f.x),__float_as_uint(f.y),
                             __float_as_uint(f.z),__float_as_uint(f.w)};
            mma_tf32(acc[mt][0], a, bB[kk*4+0], bB[kk*4+1]);
            mma_tf32(acc[mt][1], a, bB[kk*4+2], bB[kk*4+3]);
        }
#pragma unroll
    for (int mt=0;mt<2;mt++)
#pragma unroll
        for (int nt=0;nt<2;nt++){
            int row = mt*16 + (lane>>2), col = cb + nt*8 + 2*(lane&3);
            float2 v0 = {acc[mt][nt][0], acc[mt][nt][1]};
            float2 v1 = {acc[mt][nt][2], acc[mt][nt][3]};
            *(float2*)(g_tsf + (size_t)(n0+row  )*DD + col) = v0;
            *(float2*)(g_tsf + (size_t)(n0+row+8)*DD + col) = v1;
        }
    {
        const int r = tid>>3, q = tid&7;
        const float* svr = sv + (size_t)(n0+r)*DD + q*16;
        float t = 0.f;
#pragma unroll
        for (int j=0;j<4;j++){
            float4 v = *(const float4*)(svr + j*4);
            float4 g = *(const float4*)(gsw + q*16 + j*4);
            t += v.x*g.x + v.y*g.y + v.z*g.z + v.w*g.w;
        }
        t += __shfl_xor_sync(0xffffffffu, t, 1);
        t += __shfl_xor_sync(0xffffffffu, t, 2);
        t += __shfl_xor_sync(0xffffffffu, t, 4);
        if (q == 0) g_ts[n0 + r] = t;
    }
}

// ============ Main persistent kernel: 1 node/iter, 2 CTAs/SM ============
#define LKo   0
#define NGo   4224
#define TFo   8448
#define PRBo  8576
#define WSo   8608
#define STGF  8640
#define PACK  (2*STGF)        // 17280, 4096 floats
#define GWL   (PACK+4096)     // 21376, 8*20 floats padded
#define GWN   (GWL+160)       // 21536
#define SMEMF (GWN+160)       // 21696
#define SMEM_BYTES (SMEMF*4)  // 86784 B -> 2 CTAs/SM

__global__ void __launch_bounds__(256,2)
main_kernel(const float* __restrict__ neigh, const float* __restrict__ link,
            const float* __restrict__ probs, const float* __restrict__ gwn,
            const float* __restrict__ gwl, const float* __restrict__ Wlink,
            float* __restrict__ out){
    extern __shared__ float sb[];
    const int tid = threadIdx.x, lane = tid & 31, wid = tid >> 5;
    const uint32_t su = (uint32_t)__cvta_generic_to_shared(sb);

    // gate weights -> padded smem (stride 20 floats: conflict-free float4 reads)
    if (tid < 128)       sb[GWL + (tid>>4)*20 + (tid&15)] = gwl[tid];
    else                 sb[GWN + ((tid-128)>>4)*20 + (tid&15)] = gwn[tid-128];

    { // stage link_weights once; build B fragments in registers
        float4* dst = (float4*)sb;
        const float4* src = (const float4*)Wlink;
#pragma unroll
        for (int i=0;i<16;i++) dst[tid + i*256] = src[tid + i*256];
    }
    __syncthreads();
    const int cb = wid * 16;
    uint32_t bB[64];
#pragma unroll
    for (int kk=0;kk<16;kk++)
#pragma unroll
        for (int nt=0;nt<2;nt++){
            int col = cb + nt*8 + (lane>>2);
            int r0  = kk*8 + (lane&3);
            bB[kk*4+nt*2+0] = f2tf(sb[ r0    *128 + col]);
            bB[kk*4+nt*2+1] = f2tf(sb[(r0+4)*128 + col]);
        }
    __syncthreads();

    const int qg = tid & 7, kg = tid >> 3;
    const int stride = gridDim.x;
    int n = blockIdx.x;
    int buf = 0;

    auto prefetch = [&](int node, int b){
        size_t base = (size_t)node * (KNB*DD);
        uint32_t sL = su + (uint32_t)((b*STGF + LKo)*4);
        uint32_t sN = su + (uint32_t)((b*STGF + NGo)*4);
#pragma unroll
        for (int i=0;i<4;i++){
            int c = tid + i*256, row = c>>5, col = c&31;
            uint32_t off = (uint32_t)(row*SA + col*4)*4;
            cp16(sL + off, link  + base + row*128 + col*4);
            cp16(sN + off, neigh + base + row*128 + col*4);
        }
        if (tid < 32)
            cp16(su + (uint32_t)((b*STGF + TFo + tid*4)*4), g_tsf + (size_t)node*DD + tid*4);
        else if (tid < 40)
            cp16(su + (uint32_t)((b*STGF + PRBo + (tid-32)*4)*4), probs + (size_t)node*KNB + (tid-32)*4);
    };

    prefetch(n, 0);
    asm volatile("cp.async.commit_group;");

    for (; n < NN_; n += stride, buf ^= 1){
        asm volatile("cp.async.wait_group 0;");
        __syncthreads();   // stage[buf] ready AND all warps done reading stage[buf^1]

        // WAR-safe prefetch: issued only after the sync above
        int nn = n + stride;
        if (nn < NN_){
            prefetch(nn, buf^1);
            asm volatile("cp.async.commit_group;");
        }

        float* st = sb + buf*STGF;
        float* lk = st + LKo;
        float* ng = st + NGo;

        // ---- gate dot: 8 threads per k ----
        {
            float t = 0.f;
#pragma unroll
            for (int j=0;j<4;j++){
                float4 l4 = *(const float4*)(lk + kg*SA + qg*16 + j*4);
                float4 n4 = *(const float4*)(ng + kg*SA + qg*16 + j*4);
                float4 gl = *(const float4*)(sb + GWL + qg*20 + j*4);
                float4 gn = *(const float4*)(sb + GWN + qg*20 + j*4);
                t += l4.x*gl.x + l4.y*gl.y + l4.z*gl.z + l4.w*gl.w
                   + n4.x*gn.x + n4.y*gn.y + n4.z*gn.z + n4.w*gn.w;
            }
            t += __shfl_xor_sync(0xffffffffu, t, 1);
            t += __shfl_xor_sync(0xffffffffu, t, 2);
            t += __shfl_xor_sync(0xffffffffu, t, 4);
            if (qg == 0)
                st[WSo + kg] = sigf(g_ts[n] + t) / (st[PRBo + kg] * (float)KNB);
        }

        // ---- pack tf32 A fragments (each element converted once per CTA) ----
#pragma unroll
        for (int q=0;q<4;q++){
            int S = tid + q*256;
            int kk = S>>6, mt = (S>>5)&1, l = S&31;
            int r = mt*16 + (l>>2), c = kk*8 + (l&3);
            float4 v;
            v.x = __uint_as_float(f2tf(lk[ r   *SA + c  ]));
            v.y = __uint_as_float(f2tf(lk[(r+8)*SA + c  ]));
            v.z = __uint_as_float(f2tf(lk[ r   *SA + c+4]));
            v.w = __uint_as_float(f2tf(lk[(r+8)*SA + c+4]));
            *(float4*)(sb + PACK + S*4) = v;
        }
        __syncthreads();   // pack + ws visible

        // ---- MMA ----
        float acc[2][2][4];
#pragma unroll
        for (int mt=0;mt<2;mt++)
#pragma unroll
            for (int nt=0;nt<2;nt++)
#pragma unroll
                for (int j=0;j<4;j++) acc[mt][nt][j]=0.f;
#pragma unroll
        for (int kk=0;kk<16;kk++)
#pragma unroll
            for (int mt=0;mt<2;mt++){
                float4 f = *(const float4*)(sb + PACK + ((kk*2+mt)*32+lane)*4);
                uint32_t a[4] = {__float_as_uint(f.x),__float_as_uint(f.y),
                                 __float_as_uint(f.z),__float_as_uint(f.w)};
                mma_tf32(acc[mt][0], a, bB[kk*4+0], bB[kk*4+1]);
                mma_tf32(acc[mt][1], a, bB[kk*4+2], bB[kk*4+3]);
            }

        // ---- epilogue ----
        {
            const int q = lane & 3;
            const float* ws_ = st + WSo;
            const float* tf_ = st + TFo;
            float s[2][2] = {{0.f,0.f},{0.f,0.f}};
#pragma unroll
            for (int mt=0;mt<2;mt++){
                int r0 = mt*16 + (lane>>2), r1 = r0 + 8;
                float w0 = ws_[r0], w1 = ws_[r1];
#pragma unroll
                for (int nt=0;nt<2;nt++){
                    int c0 = cb + nt*8 + 2*q;
                    float2 n0 = *(const float2*)(ng + r0*SA + c0);
                    float2 n1 = *(const float2*)(ng + r1*SA + c0);
                    s[nt][0] += n0.x * sigt(acc[mt][nt][0]) * w0
                              + n1.x * sigt(acc[mt][nt][2]) * w1;
                    s[nt][1] += n0.y * sigt(acc[mt][nt][1]) * w0
                              + n1.y * sigt(acc[mt][nt][3]) * w1;
                }
            }
#pragma unroll
            for (int nt=0;nt<2;nt++)
#pragma unroll
                for (int h=0;h<2;h++){
                    s[nt][h] += __shfl_xor_sync(0xffffffffu, s[nt][h], 4);
                    s[nt][h] += __shfl_xor_sync(0xffffffffu, s[nt][h], 8);
                    s[nt][h] += __shfl_xor_sync(0xffffffffu, s[nt][h], 16);
                }
            if (lane < 4){
#pragma unroll
                for (int nt=0;nt<2;nt++){
                    int c0 = cb + nt*8 + 2*lane;
                    float2 o;
                    o.x = fmaxf(tf_[c0]   * s[nt][0], 0.f);
                    o.y = fmaxf(tf_[c0+1] * s[nt][1], 0.f);
                    *(float2*)(out + (size_t)n*DD + c0) = o;
                }
            }
        }
        // Safe: next iteration's prefetch into this stage is issued only after
        // the next top __syncthreads, which follows every warp's epilogue here.
    }
}

extern "C" void kernel_launch(void* const* d_in, const int* in_sizes, int n_in,
                              void* d_out, int out_size){
    const float* self_feats  = (const float*)d_in[0];
    const float* self_vecs   = (const float*)d_in[1];
    const float* neigh_vecs  = (const float*)d_in[2];
    const float* link_vecs   = (const float*)d_in[3];
    const float* select_pr   = (const float*)d_in[4];
    const float* gate_self_w = (const float*)d_in[5];
    const float* gate_neigh_w= (const float*)d_in[6];
    const float* gate_link_w = (const float*)d_in[7];
    const float* self_w      = (const float*)d_in[8];
    const float* link_w      = (const float*)d_in[9];
    float* out = (float*)d_out;
    (void)in_sizes; (void)n_in; (void)out_size;

    cudaFuncSetAttribute(precompute_kernel, cudaFuncAttributeMaxDynamicSharedMemorySize, P_BYTES);
    cudaFuncSetAttribute(main_kernel, cudaFuncAttributeMaxDynamicSharedMemorySize, SMEM_BYTES);

    int dev = 0, sms = 148;
    cudaGetDevice(&dev);
    cudaDeviceGetAttribute(&sms, cudaDevAttrMultiProcessorCount, dev);

    precompute_kernel<<<NN_/32, 256, P_BYTES>>>(self_feats, self_vecs, self_w, gate_self_w);
    main_kernel<<<2*sms, 256, SMEM_BYTES>>>(neigh_vecs, link_vecs, select_pr,
                                            gate_neigh_w, gate_link_w, link_w, out);
}

// round 13
// speedup vs baseline: 2.4350x; 1.4380x over previous
#include <cuda_runtime.h>
#include <cstdint>

#define NN_ 20000
#define KNB 32
#define DD  128
#define SA  132   // precompute kernel padding
#define SB_ 136   // main kernel tile row stride (conflict-free)

__device__ float g_tsf[(size_t)NN_ * DD];
__device__ float g_ts[NN_];

__device__ __forceinline__ float sigf(float x){ return 1.0f/(1.0f+__expf(-x)); }
__device__ __forceinline__ float sigt(float x){
    float t; asm("tanh.approx.f32 %0, %1;" : "=f"(t) : "f"(0.5f*x));
    return fmaf(0.5f, t, 0.5f);
}
__device__ __forceinline__ uint32_t f2tf(float f){ uint32_t o; asm("cvt.rna.tf32.f32 %0, %1;":"=r"(o):"f"(f)); return o; }
__device__ __forceinline__ void cp16(uint32_t s, const void* g){
    asm volatile("cp.async.cg.shared.global [%0], [%1], 16;"::"r"(s),"l"(g));
}
__device__ __forceinline__ void cp4(uint32_t s, const void* g){
    asm volatile("cp.async.ca.shared.global [%0], [%1], 4;"::"r"(s),"l"(g));
}
__device__ __forceinline__ void mma_tf32(float c[4], const uint32_t a[4], uint32_t b0, uint32_t b1){
    asm volatile("mma.sync.aligned.m16n8k8.row.col.f32.tf32.tf32.f32 "
        "{%0,%1,%2,%3},{%4,%5,%6,%7},{%8,%9},{%0,%1,%2,%3};"
        : "+f"(c[0]),"+f"(c[1]),"+f"(c[2]),"+f"(c[3])
        : "r"(a[0]),"r"(a[1]),"r"(a[2]),"r"(a[3]),"r"(b0),"r"(b1));
}

// ============ Kernel 1 (unchanged, proven): tsf = sf @ SW ; ts = sv . gsw ============
#define P_TILE 16384
#define P_PACK (16384+4224)
#define P_FLOATS (P_PACK+4096)
#define P_BYTES (P_FLOATS*4)

__global__ void __launch_bounds__(256,1)
precompute_kernel(const float* __restrict__ sf, const float* __restrict__ sv,
                  const float* __restrict__ SW, const float* __restrict__ gsw){
    extern __shared__ __align__(1024) float ps[];
    const int tid = threadIdx.x, lane = tid & 31, wid = tid >> 5;
    const int n0 = blockIdx.x * 32;
    {
        float4* dst = (float4*)ps;
        const float4* src = (const float4*)SW;
#pragma unroll
        for (int i=0;i<16;i++) dst[tid + i*256] = src[tid + i*256];
    }
    __syncthreads();
    const int cb = wid * 16;
    uint32_t bB[64];
#pragma unroll
    for (int kk=0;kk<16;kk++)
#pragma unroll
        for (int nt=0;nt<2;nt++){
            int col = cb + nt*8 + (lane>>2);
            int r0  = kk*8 + (lane&3);
            bB[kk*4+nt*2+0] = f2tf(ps[ r0    *128 + col]);
            bB[kk*4+nt*2+1] = f2tf(ps[(r0+4)*128 + col]);
        }
    __syncthreads();
    {
        const float4* src = (const float4*)(sf + (size_t)n0*DD);
#pragma unroll
        for (int i=0;i<4;i++){
            int c = tid + i*256, row = c>>5, col = c&31;
            *(float4*)(ps + P_TILE + row*SA + col*4) = src[c];
        }
    }
    __syncthreads();
    {
#pragma unroll
        for (int q=0;q<4;q++){
            int S = tid + q*256;
            int kk = S>>6, mt = (S>>5)&1, l = S&31;
            int r = mt*16 + (l>>2), c = kk*8 + (l&3);
            const float* t = ps + P_TILE;
            float4 v;
            v.x = __uint_as_float(f2tf(t[ r   *SA + c  ]));
            v.y = __uint_as_float(f2tf(t[(r+8)*SA + c  ]));
            v.z = __uint_as_float(f2tf(t[ r   *SA + c+4]));
            v.w = __uint_as_float(f2tf(t[(r+8)*SA + c+4]));
            *(float4*)(ps + P_PACK + S*4) = v;
        }
    }
    __syncthreads();
    float acc[2][2][4];
#pragma unroll
    for (int mt=0;mt<2;mt++)
#pragma unroll
        for (int nt=0;nt<2;nt++)
#pragma unroll
            for (int j=0;j<4;j++) acc[mt][nt][j]=0.f;
#pragma unroll
    for (int kk=0;kk<16;kk++)
#pragma unroll
        for (int mt=0;mt<2;mt++){
            float4 f = *(const float4*)(ps + P_PACK + ((kk*2+mt)*32+lane)*4);
            uint32_t a[4] = {__float_as_uint(f.x),__float_as_uint(f.y),
                             __float_as_uint(f.z),__float_as_uint(f.w)};
            mma_tf32(acc[mt][0], a, bB[kk*4+0], bB[kk*4+1]);
            mma_tf32(acc[mt][1], a, bB[kk*4+2], bB[kk*4+3]);
        }
#pragma unroll
    for (int mt=0;mt<2;mt++)
#pragma unroll
        for (int nt=0;nt<2;nt++){
            int row = mt*16 + (lane>>2), col = cb + nt*8 + 2*(lane&3);
            float2 v0 = {acc[mt][nt][0], acc[mt][nt][1]};
            float2 v1 = {acc[mt][nt][2], acc[mt][nt][3]};
            *(float2*)(g_tsf + (size_t)(n0+row  )*DD + col) = v0;
            *(float2*)(g_tsf + (size_t)(n0+row+8)*DD + col) = v1;
        }
    {
        const int r = tid>>3, q = tid&7;
        const float* svr = sv + (size_t)(n0+r)*DD + q*16;
        float t = 0.f;
#pragma unroll
        for (int j=0;j<4;j++){
            float4 v = *(const float4*)(svr + j*4);
            float4 g = *(const float4*)(gsw + q*16 + j*4);
            t += v.x*g.x + v.y*g.y + v.z*g.z + v.w*g.w;
        }
        t += __shfl_xor_sync(0xffffffffu, t, 1);
        t += __shfl_xor_sync(0xffffffffu, t, 2);
        t += __shfl_xor_sync(0xffffffffu, t, 4);
        if (q == 0) g_ts[n0 + r] = t;
    }
}

// ============ Main: mma.sync, no pack phase, conflict-free stride-136 tiles ============
// float offsets
#define LK0   0
#define LK1   4352
#define NG0   8704
#define NG1   13056
#define TSF0  17408
#define TSF1  17536
#define PRB0  17664
#define PRB1  17696
#define TSS0  17728
#define TSS1  17732
#define WS0   17736
#define WS1   17768
#define SCR   17800
#define SMEMF 17932
#define SMEM_BYTES (SMEMF*4)   // 71728 B -> 2 CTAs/SM

__global__ void __launch_bounds__(256,2)
main_kernel(const float* __restrict__ neigh, const float* __restrict__ link,
            const float* __restrict__ probs, const float* __restrict__ gwn,
            const float* __restrict__ gwl, const float* __restrict__ Wlink,
            float* __restrict__ out){
    extern __shared__ __align__(16) float sb[];
    const int tid = threadIdx.x, lane = tid & 31, wid = tid >> 5;
    const uint32_t su = (uint32_t)__cvta_generic_to_shared(sb);

    // stage W row-major once; build B fragments with PERMUTED rows:
    // logical contract index 8kk+q  <-> physical 8kk+2q
    //                        8kk+q+4 <-> physical 8kk+2q+1
    {
        float4* dst = (float4*)sb;
        const float4* src = (const float4*)Wlink;
#pragma unroll
        for (int i=0;i<16;i++) dst[tid + i*256] = src[tid + i*256];
    }
    __syncthreads();
    const int cb = wid * 16;
    uint32_t bB[64];
#pragma unroll
    for (int kk=0;kk<16;kk++)
#pragma unroll
        for (int nt=0;nt<2;nt++){
            int col = cb + nt*8 + (lane>>2);
            int r0  = kk*8 + 2*(lane&3);     // physical row of logical (kk*8 + q)
            bB[kk*4+nt*2+0] = f2tf(sb[ r0   *128 + col]);
            bB[kk*4+nt*2+1] = f2tf(sb[(r0+1)*128 + col]);  // logical (kk*8+q+4)
        }
    __syncthreads();

    // gate weights in regs, chunk order rotated by qg>>1 (bank spread of smem reads)
    const int qg = tid & 7, kg = tid >> 3;
    const int rot = qg >> 1;
    float4 gl4[4], gn4[4];
#pragma unroll
    for (int jj=0;jj<4;jj++){
        int j = (jj + rot) & 3;
        gl4[jj] = *(const float4*)(gwl + qg*16 + j*4);
        gn4[jj] = *(const float4*)(gwn + qg*16 + j*4);
    }

    const int stride = gridDim.x;
    int n = blockIdx.x;
    int buf = 0;

    auto prefetch = [&](int node, int b){
        size_t base = (size_t)node * (KNB*DD);
        uint32_t sL = su + (uint32_t)((b?LK1:LK0)*4);
        uint32_t sN = su + (uint32_t)((b?NG1:NG0)*4);
#pragma unroll
        for (int i=0;i<4;i++){
            int c = tid + i*256, row = c>>5, c16 = c&31;
            uint32_t off = (uint32_t)(row*SB_ + c16*4)*4;
            cp16(sL + off, link  + base + row*128 + c16*4);
            cp16(sN + off, neigh + base + row*128 + c16*4);
        }
        if (tid < 32)
            cp16(su + (uint32_t)(((b?TSF1:TSF0) + tid*4)*4), g_tsf + (size_t)node*DD + tid*4);
        else if (tid < 40)
            cp16(su + (uint32_t)(((b?PRB1:PRB0) + (tid-32)*4)*4), probs + (size_t)node*KNB + (tid-32)*4);
        else if (tid == 40)
            cp4(su + (uint32_t)((b?TSS1:TSS0)*4), g_ts + node);
    };

    prefetch(n, 0);
    asm volatile("cp.async.commit_group;");

    for (; n < NN_; n += stride, buf ^= 1){
        asm volatile("cp.async.wait_group 0;");
        __syncthreads();   // stage[buf] ready AND all prior-iter reads done

        int nn = n + stride;
        if (nn < NN_){
            prefetch(nn, buf^1);
            asm volatile("cp.async.commit_group;");
        }

        const float* lk = sb + (buf?LK1:LK0);
        const float* ng = sb + (buf?NG1:NG0);
        float* ws       = sb + (buf?WS1:WS0);
        const float* pb = sb + (buf?PRB1:PRB0);
        const float* tf = sb + (buf?TSF1:TSF0);
        const float tsv = sb[buf?TSS1:TSS0];

        // ---- gate dot: 8 threads per k, rotated chunk order (conflict-free) ----
        {
            float t = 0.f;
#pragma unroll
            for (int jj=0;jj<4;jj++){
                int j = (jj + rot) & 3;
                float4 l4 = *(const float4*)(lk + kg*SB_ + qg*16 + j*4);
                float4 n4 = *(const float4*)(ng + kg*SB_ + qg*16 + j*4);
                t += l4.x*gl4[jj].x + l4.y*gl4[jj].y + l4.z*gl4[jj].z + l4.w*gl4[jj].w
                   + n4.x*gn4[jj].x + n4.y*gn4[jj].y + n4.z*gn4[jj].z + n4.w*gn4[jj].w;
            }
            t += __shfl_xor_sync(0xffffffffu, t, 1);
            t += __shfl_xor_sync(0xffffffffu, t, 2);
            t += __shfl_xor_sync(0xffffffffu, t, 4);
            if (qg == 0)
                ws[kg] = sigf(tsv + t) / (pb[kg] * (float)KNB);
        }
        __syncthreads();   // ws visible

        // ---- MMA: A fragments straight from the tile (LDS.64 pairs, no cvt:
        //      raw fp32 bits -> HW tf32 truncation). Permuted columns make the
        //      (q, q+4) logical pair physically adjacent. ----
        float acc[2][2][4];
#pragma unroll
        for (int mt=0;mt<2;mt++)
#pragma unroll
            for (int nt=0;nt<2;nt++)
#pragma unroll
                for (int j=0;j<4;j++) acc[mt][nt][j]=0.f;

        const float* abase = lk + 2*(lane&3);
#pragma unroll
        for (int kk=0;kk<16;kk++){
#pragma unroll
            for (int mt=0;mt<2;mt++){
                int r = mt*16 + (lane>>2);
                float2 lo = *(const float2*)(abase + r*SB_     + kk*8);
                float2 hi = *(const float2*)(abase + (r+8)*SB_ + kk*8);
                uint32_t a[4] = {__float_as_uint(lo.x), __float_as_uint(hi.x),
                                 __float_as_uint(lo.y), __float_as_uint(hi.y)};
                mma_tf32(acc[mt][0], a, bB[kk*4+0], bB[kk*4+1]);
                mma_tf32(acc[mt][1], a, bB[kk*4+2], bB[kk*4+3]);
            }
        }

        // ---- epilogue ----
        {
            const int q = lane & 3;
            float s[2][2] = {{0.f,0.f},{0.f,0.f}};
#pragma unroll
            for (int mt=0;mt<2;mt++){
                int r0 = mt*16 + (lane>>2), r1 = r0 + 8;
                float w0 = ws[r0], w1 = ws[r1];
#pragma unroll
                for (int nt=0;nt<2;nt++){
                    int c0 = cb + nt*8 + 2*q;
                    float2 n0 = *(const float2*)(ng + r0*SB_ + c0);
                    float2 n1 = *(const float2*)(ng + r1*SB_ + c0);
                    s[nt][0] += n0.x * sigt(acc[mt][nt][0]) * w0
                              + n1.x * sigt(acc[mt][nt][2]) * w1;
                    s[nt][1] += n0.y * sigt(acc[mt][nt][1]) * w0
                              + n1.y * sigt(acc[mt][nt][3]) * w1;
                }
            }
#pragma unroll
            for (int nt=0;nt<2;nt++)
#pragma unroll
                for (int h=0;h<2;h++){
                    s[nt][h] += __shfl_xor_sync(0xffffffffu, s[nt][h], 4);
                    s[nt][h] += __shfl_xor_sync(0xffffffffu, s[nt][h], 8);
                    s[nt][h] += __shfl_xor_sync(0xffffffffu, s[nt][h], 16);
                }
            if (lane < 4){
#pragma unroll
                for (int nt=0;nt<2;nt++){
                    int c0 = cb + nt*8 + 2*lane;
                    float2 o;
                    o.x = fmaxf(tf[c0]   * s[nt][0], 0.f);
                    o.y = fmaxf(tf[c0+1] * s[nt][1], 0.f);
                    *(float2*)(out + (size_t)n*DD + c0) = o;
                }
            }
        }
        // WAR on this stage is guarded by the next iteration's top __syncthreads
        // (prefetch is issued only after it).
    }
}

extern "C" void kernel_launch(void* const* d_in, const int* in_sizes, int n_in,
                              void* d_out, int out_size){
    const float* self_feats  = (const float*)d_in[0];
    const float* self_vecs   = (const float*)d_in[1];
    const float* neigh_vecs  = (const float*)d_in[2];
    const float* link_vecs   = (const float*)d_in[3];
    const float* select_pr   = (const float*)d_in[4];
    const float* gate_self_w = (const float*)d_in[5];
    const float* gate_neigh_w= (const float*)d_in[6];
    const float* gate_link_w = (const float*)d_in[7];
    const float* self_w      = (const float*)d_in[8];
    const float* link_w      = (const float*)d_in[9];
    float* out = (float*)d_out;
    (void)in_sizes; (void)n_in; (void)out_size;

    cudaFuncSetAttribute(precompute_kernel, cudaFuncAttributeMaxDynamicSharedMemorySize, P_BYTES);
    cudaFuncSetAttribute(main_kernel, cudaFuncAttributeMaxDynamicSharedMemorySize, SMEM_BYTES);

    int dev = 0, sms = 148;
    cudaGetDevice(&dev);
    cudaDeviceGetAttribute(&sms, cudaDevAttrMultiProcessorCount, dev);

    precompute_kernel<<<NN_/32, 256, P_BYTES>>>(self_feats, self_vecs, self_w, gate_self_w);
    main_kernel<<<2*sms, 256, SMEM_BYTES>>>(neigh_vecs, link_vecs, select_pr,
                                            gate_neigh_w, gate_link_w, link_w, out);
}